// round 1
// baseline (speedup 1.0000x reference)
#include <cuda_runtime.h>
#include <math.h>

#define T 2048
#define H 1024
#define F 4096
#define E 8

// ---------------- scratch (static device globals; no allocation) ----------------
__device__ int   g_cnt[E];
__device__ int   g_tok[E][T];
__device__ float g_wt[E][T];
__device__ float g_act[(size_t)E * T * F];   // [e][slot][F] activation scratch

// ---------------- init: zero counters and output ----------------
__global__ void init_kernel(float* __restrict__ out) {
    int idx = blockIdx.x * blockDim.x + threadIdx.x;
    if (idx < E) g_cnt[idx] = 0;
    int stride = gridDim.x * blockDim.x;
    for (int i = idx; i < T * H; i += stride) out[i] = 0.0f;
}

// ---------------- router: logits -> softcap -> softmax -> top2 ----------------
__global__ void router_kernel(const float* __restrict__ hs, const float* __restrict__ gw) {
    int t = blockIdx.x;
    int tid = threadIdx.x;
    int w = tid >> 5, lane = tid & 31;   // 8 warps = 8 experts
    const float* hrow = hs + (size_t)t * H;
    const float* grow = gw + (size_t)w * H;
    float s = 0.0f;
    for (int j = lane; j < H; j += 32) s += hrow[j] * grow[j];
    #pragma unroll
    for (int o = 16; o; o >>= 1) s += __shfl_xor_sync(0xffffffffu, s, o);
    __shared__ float s_logit[E];
    if (lane == 0) s_logit[w] = s;
    __syncthreads();
    if (tid == 0) {
        float l[E], m = -1e30f;
        #pragma unroll
        for (int e = 0; e < E; e++) {
            l[e] = 30.0f * tanhf(s_logit[e] * (1.0f / 30.0f));
            m = fmaxf(m, l[e]);
        }
        float p[E], sum = 0.0f;
        #pragma unroll
        for (int e = 0; e < E; e++) { p[e] = expf(l[e] - m); sum += p[e]; }
        float inv = 1.0f / sum;
        #pragma unroll
        for (int e = 0; e < E; e++) p[e] *= inv;
        // top-1 (strict > keeps lowest index on ties, matching jax.lax.top_k)
        int e1 = 0;
        #pragma unroll
        for (int e = 1; e < E; e++) if (p[e] > p[e1]) e1 = e;
        int e2 = (e1 == 0) ? 1 : 0;
        #pragma unroll
        for (int e = 0; e < E; e++) if (e != e1 && p[e] > p[e2]) e2 = e;
        int pos1 = atomicAdd(&g_cnt[e1], 1);
        g_tok[e1][pos1] = t; g_wt[e1][pos1] = p[e1];
        int pos2 = atomicAdd(&g_cnt[e2], 1);
        g_tok[e2][pos2] = t; g_wt[e2][pos2] = p[e2];
    }
}

// ---------------- gemm1: act = gelu(h@w1^T) * (h@w3^T), grouped by expert ----------------
// Tile: BM1=128, BN1=64, BK=16. 256 threads, each 8x4 microtile, dual accumulators.
#define BM1 128
#define BN1 64
#define BK  16

__global__ __launch_bounds__(256) void gemm1_kernel(const float* __restrict__ hs,
                                                    const float* __restrict__ w1,
                                                    const float* __restrict__ w3) {
    int e = blockIdx.z;
    int cnt = g_cnt[e];
    int i0 = blockIdx.y * BM1;
    if (i0 >= cnt) return;
    int n0 = blockIdx.x * BN1;

    __shared__ float As [BK][BM1 + 4];
    __shared__ float Bs1[BK][BN1 + 4];
    __shared__ float Bs3[BK][BN1 + 4];
    __shared__ int   s_tok[BM1];

    int tid = threadIdx.x;
    if (tid < BM1) {
        int i = i0 + tid;
        s_tok[tid] = (i < cnt) ? g_tok[e][i] : -1;
    }
    __syncthreads();

    int lr = tid >> 2;            // 0..63
    int kq = (tid & 3) * 4;       // 0,4,8,12
    int ty = tid >> 4;            // 0..15 -> m-octet
    int tx = tid & 15;            // 0..15 -> n-quad

    const float* w1b = w1 + ((size_t)e * F + n0) * H;
    const float* w3b = w3 + ((size_t)e * F + n0) * H;

    float acc1[8][4], acc3[8][4];
    #pragma unroll
    for (int i = 0; i < 8; i++)
        #pragma unroll
        for (int j = 0; j < 4; j++) { acc1[i][j] = 0.0f; acc3[i][j] = 0.0f; }

    for (int k0 = 0; k0 < H; k0 += BK) {
        #pragma unroll
        for (int h2 = 0; h2 < 2; h2++) {
            int m = lr + h2 * 64;
            int tok = s_tok[m];
            float4 v = make_float4(0.f, 0.f, 0.f, 0.f);
            if (tok >= 0)
                v = *reinterpret_cast<const float4*>(hs + (size_t)tok * H + k0 + kq);
            As[kq + 0][m] = v.x; As[kq + 1][m] = v.y;
            As[kq + 2][m] = v.z; As[kq + 3][m] = v.w;
        }
        {
            float4 v = *reinterpret_cast<const float4*>(w1b + (size_t)lr * H + k0 + kq);
            Bs1[kq + 0][lr] = v.x; Bs1[kq + 1][lr] = v.y;
            Bs1[kq + 2][lr] = v.z; Bs1[kq + 3][lr] = v.w;
            float4 u = *reinterpret_cast<const float4*>(w3b + (size_t)lr * H + k0 + kq);
            Bs3[kq + 0][lr] = u.x; Bs3[kq + 1][lr] = u.y;
            Bs3[kq + 2][lr] = u.z; Bs3[kq + 3][lr] = u.w;
        }
        __syncthreads();
        #pragma unroll
        for (int k = 0; k < BK; k++) {
            float a[8], b1[4], b3[4];
            #pragma unroll
            for (int i = 0; i < 8; i++) a[i] = As[k][ty * 8 + i];
            #pragma unroll
            for (int j = 0; j < 4; j++) { b1[j] = Bs1[k][tx * 4 + j]; b3[j] = Bs3[k][tx * 4 + j]; }
            #pragma unroll
            for (int i = 0; i < 8; i++)
                #pragma unroll
                for (int j = 0; j < 4; j++) {
                    acc1[i][j] += a[i] * b1[j];
                    acc3[i][j] += a[i] * b3[j];
                }
        }
        __syncthreads();
    }

    float* actb = g_act + (size_t)e * T * F;
    #pragma unroll
    for (int i = 0; i < 8; i++) {
        int ig = i0 + ty * 8 + i;
        if (ig >= cnt) continue;
        #pragma unroll
        for (int j = 0; j < 4; j++) {
            float g = acc1[i][j];
            float val = g * normcdff(g) * acc3[i][j];   // exact GELU gate * up-proj
            actb[(size_t)ig * F + n0 + tx * 4 + j] = val;
        }
    }
}

// ---------------- gemm2: out[token] += weight * (act @ w2^T) ----------------
// Tile: BM2=128, BN2=128, BK=16. 256 threads, 8x8 microtile.
#define BM2 128
#define BN2 128

__global__ __launch_bounds__(256) void gemm2_kernel(const float* __restrict__ w2,
                                                    float* __restrict__ out) {
    int e = blockIdx.z;
    int cnt = g_cnt[e];
    int i0 = blockIdx.y * BM2;
    if (i0 >= cnt) return;
    int n0 = blockIdx.x * BN2;

    __shared__ float As[BK][BM2 + 4];
    __shared__ float Bs[BK][BN2 + 4];
    __shared__ int   s_tok[BM2];
    __shared__ float s_wt[BM2];

    int tid = threadIdx.x;
    if (tid < BM2) {
        int i = i0 + tid;
        s_tok[tid] = (i < cnt) ? g_tok[e][i] : -1;
        s_wt[tid]  = (i < cnt) ? g_wt[e][i]  : 0.0f;
    }
    __syncthreads();

    const float* A = g_act + (size_t)(e * T + i0) * F;
    const float* B = w2 + ((size_t)e * H + n0) * F;

    int lr = tid >> 2;
    int kq = (tid & 3) * 4;
    int ty = tid >> 4;
    int tx = tid & 15;
    int mrows = min(BM2, cnt - i0);

    float acc[8][8];
    #pragma unroll
    for (int i = 0; i < 8; i++)
        #pragma unroll
        for (int j = 0; j < 8; j++) acc[i][j] = 0.0f;

    for (int k0 = 0; k0 < F; k0 += BK) {
        #pragma unroll
        for (int h2 = 0; h2 < 2; h2++) {
            int m = lr + h2 * 64;
            float4 v = make_float4(0.f, 0.f, 0.f, 0.f);
            if (m < mrows)
                v = *reinterpret_cast<const float4*>(A + (size_t)m * F + k0 + kq);
            As[kq + 0][m] = v.x; As[kq + 1][m] = v.y;
            As[kq + 2][m] = v.z; As[kq + 3][m] = v.w;
        }
        #pragma unroll
        for (int h2 = 0; h2 < 2; h2++) {
            int n = lr + h2 * 64;
            float4 v = *reinterpret_cast<const float4*>(B + (size_t)n * F + k0 + kq);
            Bs[kq + 0][n] = v.x; Bs[kq + 1][n] = v.y;
            Bs[kq + 2][n] = v.z; Bs[kq + 3][n] = v.w;
        }
        __syncthreads();
        #pragma unroll
        for (int k = 0; k < BK; k++) {
            float a[8], b[8];
            #pragma unroll
            for (int i = 0; i < 8; i++) a[i] = As[k][ty * 8 + i];
            #pragma unroll
            for (int j = 0; j < 8; j++) b[j] = Bs[k][tx * 8 + j];
            #pragma unroll
            for (int i = 0; i < 8; i++)
                #pragma unroll
                for (int j = 0; j < 8; j++) acc[i][j] += a[i] * b[j];
        }
        __syncthreads();
    }

    #pragma unroll
    for (int i = 0; i < 8; i++) {
        int m = ty * 8 + i;
        if (m >= mrows) continue;
        int tok = s_tok[m];
        float wgt = s_wt[m];
        size_t base = (size_t)tok * H + n0 + tx * 8;
        #pragma unroll
        for (int j = 0; j < 8; j++) {
            // exactly 2 atomic adds per out element (one per routed expert);
            // fp32 add is commutative => bitwise-deterministic result.
            atomicAdd(&out[base + j], wgt * acc[i][j]);
        }
    }
}

// ---------------- launch ----------------
extern "C" void kernel_launch(void* const* d_in, const int* in_sizes, int n_in,
                              void* d_out, int out_size) {
    const float* hs = (const float*)d_in[0];
    const float* gw = (const float*)d_in[1];
    const float* w1 = (const float*)d_in[2];
    const float* w2 = (const float*)d_in[3];
    const float* w3 = (const float*)d_in[4];
    float* out = (float*)d_out;

    init_kernel<<<1024, 256>>>(out);
    router_kernel<<<T, 256>>>(hs, gw);
    gemm1_kernel<<<dim3(F / BN1, (T + BM1 - 1) / BM1, E), 256>>>(hs, w1, w3);
    gemm2_kernel<<<dim3(H / BN2, (T + BM2 - 1) / BM2, E), 256>>>(w2, out);
}

// round 3
// speedup vs baseline: 2.7959x; 2.7959x over previous
#include <cuda_runtime.h>
#include <math.h>
#include <stdint.h>

#define T 2048
#define H 1024
#define F 4096
#define E 8

// ---------------- scratch (static device globals; no allocation) ----------------
__device__ int   g_cnt[E];
__device__ int   g_tok[E][T];
__device__ float g_wt[E][T];
__device__ float g_act[(size_t)E * T * F];   // [e][slot][F] activation scratch

// ================= family-safe PTX helpers (no sm_103a-only ops!) =================
__device__ __forceinline__ uint32_t smem_u32(const void* p) {
    uint32_t a;
    asm("{ .reg .u64 t; cvta.to.shared.u64 t, %1; cvt.u32.u64 %0, t; }" : "=r"(a) : "l"(p));
    return a;
}
// fp32 -> tf32 (round-to-nearest, avoids truncation bias), result in b32 reg
__device__ __forceinline__ uint32_t tf32u(float x) {
    uint32_t u; asm("cvt.rna.tf32.f32 %0, %1;" : "=r"(u) : "f"(x)); return u;
}
// d += a * b  (m16n8k8, tf32 inputs, fp32 accum)
__device__ __forceinline__ void mma_tf32(float* d, const uint32_t* a, const uint32_t* b) {
    asm volatile(
        "mma.sync.aligned.m16n8k8.row.col.f32.tf32.tf32.f32 "
        "{%0,%1,%2,%3}, {%4,%5,%6,%7}, {%8,%9}, {%0,%1,%2,%3};"
        : "+f"(d[0]), "+f"(d[1]), "+f"(d[2]), "+f"(d[3])
        : "r"(a[0]), "r"(a[1]), "r"(a[2]), "r"(a[3]), "r"(b[0]), "r"(b[1]));
}
__device__ __forceinline__ void cpa16(uint32_t dst, const void* src, uint32_t sz) {
    asm volatile("cp.async.cg.shared.global [%0], [%1], 16, %2;"
                 :: "r"(dst), "l"(src), "r"(sz) : "memory");
}
#define CPA_COMMIT() asm volatile("cp.async.commit_group;" ::: "memory")
#define CPA_WAIT(n)  asm volatile("cp.async.wait_group %0;" :: "n"(n) : "memory")

// SMEM tile pitch: 36 floats (144B; 16B-aligned, conflict-free fragment loads)
#define PITCH 36
#define BK    32

// ---------------- init ----------------
__global__ void init_kernel(float* __restrict__ out) {
    int idx = blockIdx.x * blockDim.x + threadIdx.x;
    if (idx < E) g_cnt[idx] = 0;
    int stride = gridDim.x * blockDim.x;
    for (int i = idx; i < T * H; i += stride) out[i] = 0.0f;
}

// ---------------- router (exact fp32) ----------------
__global__ void router_kernel(const float* __restrict__ hs, const float* __restrict__ gw) {
    int t = blockIdx.x;
    int tid = threadIdx.x;
    int w = tid >> 5, lane = tid & 31;
    const float* hrow = hs + (size_t)t * H;
    const float* grow = gw + (size_t)w * H;
    float s = 0.0f;
    for (int j = lane; j < H; j += 32) s += hrow[j] * grow[j];
    #pragma unroll
    for (int o = 16; o; o >>= 1) s += __shfl_xor_sync(0xffffffffu, s, o);
    __shared__ float s_logit[E];
    if (lane == 0) s_logit[w] = s;
    __syncthreads();
    if (tid == 0) {
        float l[E], m = -1e30f;
        #pragma unroll
        for (int e = 0; e < E; e++) {
            l[e] = 30.0f * tanhf(s_logit[e] * (1.0f / 30.0f));
            m = fmaxf(m, l[e]);
        }
        float p[E], sum = 0.0f;
        #pragma unroll
        for (int e = 0; e < E; e++) { p[e] = expf(l[e] - m); sum += p[e]; }
        float inv = 1.0f / sum;
        #pragma unroll
        for (int e = 0; e < E; e++) p[e] *= inv;
        int e1 = 0;
        #pragma unroll
        for (int e = 1; e < E; e++) if (p[e] > p[e1]) e1 = e;
        int e2 = (e1 == 0) ? 1 : 0;
        #pragma unroll
        for (int e = 0; e < E; e++) if (e != e1 && p[e] > p[e2]) e2 = e;
        int pos1 = atomicAdd(&g_cnt[e1], 1);
        g_tok[e1][pos1] = t; g_wt[e1][pos1] = p[e1];
        int pos2 = atomicAdd(&g_cnt[e2], 1);
        g_tok[e2][pos2] = t; g_wt[e2][pos2] = p[e2];
    }
}

// ================= gemm1: act = gelu(h@w1^T) * (h@w3^T) =================
// CTA tile 128(m) x 64(n), BK=32. 8 warps, warp tile 32x32, dual accumulators.
// dyn smem per buffer: A 128x36, B1 64x36, B3 64x36 floats = 36864B; 2 buffers.
#define G1_BUF_B   36864u
#define G1_OFF_B1  18432u
#define G1_OFF_B3  27648u
#define G1_SMEM    (2u * G1_BUF_B)

__global__ __launch_bounds__(256) void gemm1_mma(const float* __restrict__ hs,
                                                 const float* __restrict__ w1,
                                                 const float* __restrict__ w3) {
    extern __shared__ float smem[];
    __shared__ int s_tok[128];

    int e = blockIdx.z;
    int cnt = g_cnt[e];
    int i0 = blockIdx.y * 128;
    if (i0 >= cnt) return;
    int n0 = blockIdx.x * 64;
    int tid = threadIdx.x;
    int wid = tid >> 5, lane = tid & 31;
    int g = lane >> 2, t4 = lane & 3;
    int wm = wid & 3, wn = wid >> 2;       // warp tile: m 32*wm, n 32*wn

    if (tid < 128) {
        int i = i0 + tid;
        s_tok[tid] = (i < cnt) ? g_tok[e][i] : -1;
    }
    __syncthreads();

    uint32_t sb = smem_u32(smem);
    const float* w1g = w1 + ((size_t)e * F + n0) * H;
    const float* w3g = w3 + ((size_t)e * F + n0) * H;

    // ---- async stage copy: A(gathered) 1024 chunks, B1 512, B3 512 ----
    auto stage = [&](int kc, int buf) {
        int k0 = kc * BK;
        uint32_t bb = sb + (uint32_t)buf * G1_BUF_B;
        #pragma unroll
        for (int i = 0; i < 4; i++) {              // A
            int id = tid + i * 256;
            int row = id >> 3, c4 = id & 7;
            int tok = s_tok[row];
            const float* src = (tok >= 0) ? hs + (size_t)tok * H + k0 + c4 * 4 : hs;
            cpa16(bb + (uint32_t)(row * 144 + c4 * 16), src, tok >= 0 ? 16u : 0u);
        }
        #pragma unroll
        for (int i = 0; i < 2; i++) {              // B1
            int id = tid + i * 256;
            int row = id >> 3, c4 = id & 7;
            cpa16(bb + G1_OFF_B1 + (uint32_t)(row * 144 + c4 * 16),
                  w1g + (size_t)row * H + k0 + c4 * 4, 16u);
        }
        #pragma unroll
        for (int i = 0; i < 2; i++) {              // B3
            int id = tid + i * 256;
            int row = id >> 3, c4 = id & 7;
            cpa16(bb + G1_OFF_B3 + (uint32_t)(row * 144 + c4 * 16),
                  w3g + (size_t)row * H + k0 + c4 * 4, 16u);
        }
    };

    float acc1[2][4][4], acc3[2][4][4];
    #pragma unroll
    for (int a = 0; a < 2; a++)
        #pragma unroll
        for (int b = 0; b < 4; b++)
            #pragma unroll
            for (int c = 0; c < 4; c++) { acc1[a][b][c] = 0.f; acc3[a][b][c] = 0.f; }

    stage(0, 0); CPA_COMMIT();

    const int NK = H / BK;   // 32
    for (int kc = 0; kc < NK; kc++) {
        int cur = kc & 1;
        if (kc + 1 < NK) { stage(kc + 1, cur ^ 1); CPA_COMMIT(); CPA_WAIT(1); }
        else             { CPA_WAIT(0); }
        __syncthreads();

        const float* As  = smem + cur * (G1_BUF_B / 4);
        const float* B1s = As + G1_OFF_B1 / 4;
        const float* B3s = As + G1_OFF_B3 / 4;

        #pragma unroll
        for (int ks = 0; ks < 4; ks++) {
            int kk = ks * 8 + t4;
            uint32_t a[2][4];
            #pragma unroll
            for (int fm = 0; fm < 2; fm++) {
                int r = wm * 32 + fm * 16 + g;
                a[fm][0] = tf32u(As[r * PITCH + kk]);
                a[fm][1] = tf32u(As[(r + 8) * PITCH + kk]);
                a[fm][2] = tf32u(As[r * PITCH + kk + 4]);
                a[fm][3] = tf32u(As[(r + 8) * PITCH + kk + 4]);
            }
            uint32_t b1[4][2], b3[4][2];
            #pragma unroll
            for (int fn = 0; fn < 4; fn++) {
                int r = wn * 32 + fn * 8 + g;
                b1[fn][0] = tf32u(B1s[r * PITCH + kk]);
                b1[fn][1] = tf32u(B1s[r * PITCH + kk + 4]);
                b3[fn][0] = tf32u(B3s[r * PITCH + kk]);
                b3[fn][1] = tf32u(B3s[r * PITCH + kk + 4]);
            }
            #pragma unroll
            for (int fm = 0; fm < 2; fm++)
                #pragma unroll
                for (int fn = 0; fn < 4; fn++) {
                    mma_tf32(acc1[fm][fn], a[fm], b1[fn]);
                    mma_tf32(acc3[fm][fn], a[fm], b3[fn]);
                }
        }
        __syncthreads();
    }

    // ---- epilogue: gelu(acc1)*acc3 -> g_act ----
    float* actb = g_act + (size_t)e * T * F;
    #pragma unroll
    for (int fm = 0; fm < 2; fm++) {
        int ml = wm * 32 + fm * 16 + g;
        #pragma unroll
        for (int fn = 0; fn < 4; fn++) {
            int col = n0 + wn * 32 + fn * 8 + 2 * t4;
            int ig0 = i0 + ml, ig1 = ig0 + 8;
            if (ig0 < cnt) {
                float g0 = acc1[fm][fn][0], g1 = acc1[fm][fn][1];
                float2 v = make_float2(g0 * normcdff(g0) * acc3[fm][fn][0],
                                       g1 * normcdff(g1) * acc3[fm][fn][1]);
                *reinterpret_cast<float2*>(actb + (size_t)ig0 * F + col) = v;
            }
            if (ig1 < cnt) {
                float g2 = acc1[fm][fn][2], g3 = acc1[fm][fn][3];
                float2 v = make_float2(g2 * normcdff(g2) * acc3[fm][fn][2],
                                       g3 * normcdff(g3) * acc3[fm][fn][3]);
                *reinterpret_cast<float2*>(actb + (size_t)ig1 * F + col) = v;
            }
        }
    }
}

// ================= gemm2: out[tok] += wgt * (act @ w2^T) =================
// CTA tile 128(m) x 128(n), BK=32. 8 warps, warp tile 32x64.
// dyn smem per buffer: A 128x36 + B 128x36 floats = 36864B; 2 buffers.
#define G2_BUF_B  36864u
#define G2_OFF_B  18432u
#define G2_SMEM   (2u * G2_BUF_B)

__global__ __launch_bounds__(256) void gemm2_mma(const float* __restrict__ w2,
                                                 float* __restrict__ out) {
    extern __shared__ float smem[];
    __shared__ int   s_tok[128];
    __shared__ float s_wt[128];

    int e = blockIdx.z;
    int cnt = g_cnt[e];
    int i0 = blockIdx.y * 128;
    if (i0 >= cnt) return;
    int n0 = blockIdx.x * 128;
    int tid = threadIdx.x;
    int wid = tid >> 5, lane = tid & 31;
    int g = lane >> 2, t4 = lane & 3;
    int wm = wid & 3, wn = wid >> 2;       // warp tile: m 32*wm, n 64*wn
    int mrows = min(128, cnt - i0);

    if (tid < 128) {
        int i = i0 + tid;
        s_tok[tid] = (i < cnt) ? g_tok[e][i] : -1;
        s_wt[tid]  = (i < cnt) ? g_wt[e][i]  : 0.0f;
    }
    __syncthreads();

    uint32_t sb = smem_u32(smem);
    const float* Ag = g_act + ((size_t)e * T + i0) * F;
    const float* Bg = w2 + ((size_t)e * H + n0) * F;

    auto stage = [&](int kc, int buf) {
        int k0 = kc * BK;
        uint32_t bb = sb + (uint32_t)buf * G2_BUF_B;
        #pragma unroll
        for (int i = 0; i < 4; i++) {              // A (ragged)
            int id = tid + i * 256;
            int row = id >> 3, c4 = id & 7;
            bool v = row < mrows;
            const float* src = v ? Ag + (size_t)row * F + k0 + c4 * 4 : Ag;
            cpa16(bb + (uint32_t)(row * 144 + c4 * 16), src, v ? 16u : 0u);
        }
        #pragma unroll
        for (int i = 0; i < 4; i++) {              // B
            int id = tid + i * 256;
            int row = id >> 3, c4 = id & 7;
            cpa16(bb + G2_OFF_B + (uint32_t)(row * 144 + c4 * 16),
                  Bg + (size_t)row * F + k0 + c4 * 4, 16u);
        }
    };

    float acc[2][8][4];
    #pragma unroll
    for (int a = 0; a < 2; a++)
        #pragma unroll
        for (int b = 0; b < 8; b++)
            #pragma unroll
            for (int c = 0; c < 4; c++) acc[a][b][c] = 0.f;

    stage(0, 0); CPA_COMMIT();

    const int NK = F / BK;   // 128
    for (int kc = 0; kc < NK; kc++) {
        int cur = kc & 1;
        if (kc + 1 < NK) { stage(kc + 1, cur ^ 1); CPA_COMMIT(); CPA_WAIT(1); }
        else             { CPA_WAIT(0); }
        __syncthreads();

        const float* As = smem + cur * (G2_BUF_B / 4);
        const float* Bs = As + G2_OFF_B / 4;

        #pragma unroll
        for (int ks = 0; ks < 4; ks++) {
            int kk = ks * 8 + t4;
            uint32_t a[2][4];
            #pragma unroll
            for (int fm = 0; fm < 2; fm++) {
                int r = wm * 32 + fm * 16 + g;
                a[fm][0] = tf32u(As[r * PITCH + kk]);
                a[fm][1] = tf32u(As[(r + 8) * PITCH + kk]);
                a[fm][2] = tf32u(As[r * PITCH + kk + 4]);
                a[fm][3] = tf32u(As[(r + 8) * PITCH + kk + 4]);
            }
            uint32_t b[8][2];
            #pragma unroll
            for (int fn = 0; fn < 8; fn++) {
                int r = wn * 64 + fn * 8 + g;
                b[fn][0] = tf32u(Bs[r * PITCH + kk]);
                b[fn][1] = tf32u(Bs[r * PITCH + kk + 4]);
            }
            #pragma unroll
            for (int fm = 0; fm < 2; fm++)
                #pragma unroll
                for (int fn = 0; fn < 8; fn++)
                    mma_tf32(acc[fm][fn], a[fm], b[fn]);
        }
        __syncthreads();
    }

    // ---- epilogue: 2 deterministic atomic adds per out element ----
    #pragma unroll
    for (int fm = 0; fm < 2; fm++) {
        int ml0 = wm * 32 + fm * 16 + g;
        int ml1 = ml0 + 8;
        int tok0 = s_tok[ml0], tok1 = s_tok[ml1];
        float w0 = s_wt[ml0], w1v = s_wt[ml1];
        #pragma unroll
        for (int fn = 0; fn < 8; fn++) {
            int col = n0 + wn * 64 + fn * 8 + 2 * t4;
            if (tok0 >= 0) {
                float* o = out + (size_t)tok0 * H + col;
                atomicAdd(o,     w0 * acc[fm][fn][0]);
                atomicAdd(o + 1, w0 * acc[fm][fn][1]);
            }
            if (tok1 >= 0) {
                float* o = out + (size_t)tok1 * H + col;
                atomicAdd(o,     w1v * acc[fm][fn][2]);
                atomicAdd(o + 1, w1v * acc[fm][fn][3]);
            }
        }
    }
}

// ---------------- launch ----------------
extern "C" void kernel_launch(void* const* d_in, const int* in_sizes, int n_in,
                              void* d_out, int out_size) {
    const float* hs = (const float*)d_in[0];
    const float* gw = (const float*)d_in[1];
    const float* w1 = (const float*)d_in[2];
    const float* w2 = (const float*)d_in[3];
    const float* w3 = (const float*)d_in[4];
    float* out = (float*)d_out;

    cudaFuncSetAttribute(gemm1_mma, cudaFuncAttributeMaxDynamicSharedMemorySize, G1_SMEM);
    cudaFuncSetAttribute(gemm2_mma, cudaFuncAttributeMaxDynamicSharedMemorySize, G2_SMEM);

    init_kernel<<<1024, 256>>>(out);
    router_kernel<<<T, 256>>>(hs, gw);
    gemm1_mma<<<dim3(F / 64, T / 128, E), 256, G1_SMEM>>>(hs, w1, w3);
    gemm2_mma<<<dim3(H / 128, T / 128, E), 256, G2_SMEM>>>(w2, out);
}

// round 4
// speedup vs baseline: 4.9642x; 1.7755x over previous
#include <cuda_runtime.h>
#include <cuda_fp16.h>
#include <math.h>
#include <stdint.h>

#define T 2048
#define H 1024
#define F 4096
#define E 8

// ---------------- scratch (static device globals; no allocation) ----------------
__device__ int    g_cnt[E];
__device__ int    g_tok[E][T];
__device__ float  g_wt[E][T];
__device__ __half g_act[(size_t)E * T * F];      // fp16 activation scratch
__device__ __half c_hs[(size_t)T * H];           // fp16 copies of inputs
__device__ __half c_w1[(size_t)E * F * H];
__device__ __half c_w3[(size_t)E * F * H];
__device__ __half c_w2[(size_t)E * H * F];

// ================= family-safe PTX helpers =================
__device__ __forceinline__ uint32_t smem_u32(const void* p) {
    uint32_t a;
    asm("{ .reg .u64 t; cvta.to.shared.u64 t, %1; cvt.u32.u64 %0, t; }" : "=r"(a) : "l"(p));
    return a;
}
// d += a * b  (m16n8k16, fp16 inputs, fp32 accum)
__device__ __forceinline__ void mma_f16(float* d, const uint32_t* a, const uint32_t* b) {
    asm volatile(
        "mma.sync.aligned.m16n8k16.row.col.f32.f16.f16.f32 "
        "{%0,%1,%2,%3}, {%4,%5,%6,%7}, {%8,%9}, {%0,%1,%2,%3};"
        : "+f"(d[0]), "+f"(d[1]), "+f"(d[2]), "+f"(d[3])
        : "r"(a[0]), "r"(a[1]), "r"(a[2]), "r"(a[3]), "r"(b[0]), "r"(b[1]));
}
__device__ __forceinline__ void cpa16(uint32_t dst, const void* src, uint32_t sz) {
    asm volatile("cp.async.cg.shared.global [%0], [%1], 16, %2;"
                 :: "r"(dst), "l"(src), "r"(sz) : "memory");
}
#define CPA_COMMIT() asm volatile("cp.async.commit_group;" ::: "memory")
#define CPA_WAIT(n)  asm volatile("cp.async.wait_group %0;" :: "n"(n) : "memory")

__device__ __forceinline__ uint32_t lds32(const __half* base, int idx_halfs) {
    return *reinterpret_cast<const uint32_t*>(base + idx_halfs);
}

// SMEM tile pitch: 72 halfs (144B). (36g + t4) mod 32 = 4g + t4 -> conflict-free.
#define PH 72
#define BK 64
#define STAGES 3

// ---------------- init ----------------
__global__ void init_kernel(float* __restrict__ out) {
    int idx = blockIdx.x * blockDim.x + threadIdx.x;
    if (idx < E) g_cnt[idx] = 0;
    int stride = gridDim.x * blockDim.x;
    for (int i = idx; i < T * H; i += stride) out[i] = 0.0f;
}

// ---------------- fp32 -> fp16 bulk convert ----------------
__global__ void cvt_kernel(const float4* __restrict__ src, uint2* __restrict__ dst, int n4) {
    int i = blockIdx.x * blockDim.x + threadIdx.x;
    int stride = gridDim.x * blockDim.x;
    for (; i < n4; i += stride) {
        float4 v = src[i];
        __half2 h0 = __floats2half2_rn(v.x, v.y);
        __half2 h1 = __floats2half2_rn(v.z, v.w);
        uint2 o;
        o.x = *reinterpret_cast<uint32_t*>(&h0);
        o.y = *reinterpret_cast<uint32_t*>(&h1);
        dst[i] = o;
    }
}

// ---------------- router (exact fp32) ----------------
__global__ void router_kernel(const float* __restrict__ hs, const float* __restrict__ gw) {
    int t = blockIdx.x;
    int tid = threadIdx.x;
    int w = tid >> 5, lane = tid & 31;
    const float* hrow = hs + (size_t)t * H;
    const float* grow = gw + (size_t)w * H;
    float s = 0.0f;
    for (int j = lane; j < H; j += 32) s += hrow[j] * grow[j];
    #pragma unroll
    for (int o = 16; o; o >>= 1) s += __shfl_xor_sync(0xffffffffu, s, o);
    __shared__ float s_logit[E];
    if (lane == 0) s_logit[w] = s;
    __syncthreads();
    if (tid == 0) {
        float l[E], m = -1e30f;
        #pragma unroll
        for (int e = 0; e < E; e++) {
            l[e] = 30.0f * tanhf(s_logit[e] * (1.0f / 30.0f));
            m = fmaxf(m, l[e]);
        }
        float p[E], sum = 0.0f;
        #pragma unroll
        for (int e = 0; e < E; e++) { p[e] = expf(l[e] - m); sum += p[e]; }
        float inv = 1.0f / sum;
        #pragma unroll
        for (int e = 0; e < E; e++) p[e] *= inv;
        int e1 = 0;
        #pragma unroll
        for (int e = 1; e < E; e++) if (p[e] > p[e1]) e1 = e;
        int e2 = (e1 == 0) ? 1 : 0;
        #pragma unroll
        for (int e = 0; e < E; e++) if (e != e1 && p[e] > p[e2]) e2 = e;
        int pos1 = atomicAdd(&g_cnt[e1], 1);
        g_tok[e1][pos1] = t; g_wt[e1][pos1] = p[e1];
        int pos2 = atomicAdd(&g_cnt[e2], 1);
        g_tok[e2][pos2] = t; g_wt[e2][pos2] = p[e2];
    }
}

// ================= gemm1: act = gelu(h@w1^T) * (h@w3^T), fp16 mma =================
// CTA 128m x 64n, BK=64, 8 warps (warp 32x32), 3-stage cp.async.
// stage: A 128*144 + B1 64*144 + B3 64*144 = 36864B; x3 = 110592B.
#define G1_STAGE_B 36864u
#define G1_OFF_B1  18432u
#define G1_OFF_B3  27648u
#define G1_SMEM    (STAGES * G1_STAGE_B)

__global__ __launch_bounds__(256) void gemm1_mma(const float* __restrict__ dummy) {
    extern __shared__ __half smem[];
    __shared__ int s_tok[128];

    int e = blockIdx.z;
    int cnt = g_cnt[e];
    int i0 = blockIdx.y * 128;
    if (i0 >= cnt) return;
    int n0 = blockIdx.x * 64;
    int tid = threadIdx.x;
    int wid = tid >> 5, lane = tid & 31;
    int g = lane >> 2, t4 = lane & 3;
    int wm = wid & 3, wn = wid >> 2;       // warp tile: m 32*wm, n 32*wn

    if (tid < 128) {
        int i = i0 + tid;
        s_tok[tid] = (i < cnt) ? g_tok[e][i] : -1;
    }
    __syncthreads();

    uint32_t sb = smem_u32(smem);
    const __half* w1g = c_w1 + ((size_t)e * F + n0) * H;
    const __half* w3g = c_w3 + ((size_t)e * F + n0) * H;

    auto stage = [&](int kc, int buf) {
        int k0 = kc * BK;
        uint32_t bb = sb + (uint32_t)buf * G1_STAGE_B;
        #pragma unroll
        for (int i = 0; i < 4; i++) {              // A gathered: 128 rows x 8 chunks
            int id = tid + i * 256;
            int row = id >> 3, c4 = id & 7;
            int tok = s_tok[row];
            const __half* src = (tok >= 0) ? c_hs + (size_t)tok * H + k0 + c4 * 8 : c_hs;
            cpa16(bb + (uint32_t)(row * 144 + c4 * 16), src, tok >= 0 ? 16u : 0u);
        }
        #pragma unroll
        for (int i = 0; i < 2; i++) {              // B1: 64 rows x 8 chunks
            int id = tid + i * 256;
            int row = id >> 3, c4 = id & 7;
            cpa16(bb + G1_OFF_B1 + (uint32_t)(row * 144 + c4 * 16),
                  w1g + (size_t)row * H + k0 + c4 * 8, 16u);
        }
        #pragma unroll
        for (int i = 0; i < 2; i++) {              // B3
            int id = tid + i * 256;
            int row = id >> 3, c4 = id & 7;
            cpa16(bb + G1_OFF_B3 + (uint32_t)(row * 144 + c4 * 16),
                  w3g + (size_t)row * H + k0 + c4 * 8, 16u);
        }
    };

    float acc1[2][4][4], acc3[2][4][4];
    #pragma unroll
    for (int a = 0; a < 2; a++)
        #pragma unroll
        for (int b = 0; b < 4; b++)
            #pragma unroll
            for (int c = 0; c < 4; c++) { acc1[a][b][c] = 0.f; acc3[a][b][c] = 0.f; }

    stage(0, 0); CPA_COMMIT();
    stage(1, 1); CPA_COMMIT();

    const int NK = H / BK;   // 16
    for (int kc = 0; kc < NK; kc++) {
        int cur = kc % STAGES;
        CPA_WAIT(1);
        __syncthreads();
        if (kc + 2 < NK) stage(kc + 2, (kc + 2) % STAGES);
        CPA_COMMIT();

        const __half* As  = smem + cur * (G1_STAGE_B / 2);
        const __half* B1s = As + G1_OFF_B1 / 2;
        const __half* B3s = As + G1_OFF_B3 / 2;

        #pragma unroll
        for (int ks = 0; ks < 4; ks++) {           // 4 x k16
            int kk = ks * 16 + 2 * t4;
            uint32_t a[2][4];
            #pragma unroll
            for (int fm = 0; fm < 2; fm++) {
                int r = wm * 32 + fm * 16 + g;
                a[fm][0] = lds32(As, r * PH + kk);
                a[fm][1] = lds32(As, (r + 8) * PH + kk);
                a[fm][2] = lds32(As, r * PH + kk + 8);
                a[fm][3] = lds32(As, (r + 8) * PH + kk + 8);
            }
            uint32_t b1[4][2], b3[4][2];
            #pragma unroll
            for (int fn = 0; fn < 4; fn++) {
                int r = wn * 32 + fn * 8 + g;
                b1[fn][0] = lds32(B1s, r * PH + kk);
                b1[fn][1] = lds32(B1s, r * PH + kk + 8);
                b3[fn][0] = lds32(B3s, r * PH + kk);
                b3[fn][1] = lds32(B3s, r * PH + kk + 8);
            }
            #pragma unroll
            for (int fm = 0; fm < 2; fm++)
                #pragma unroll
                for (int fn = 0; fn < 4; fn++) {
                    mma_f16(acc1[fm][fn], a[fm], b1[fn]);
                    mma_f16(acc3[fm][fn], a[fm], b3[fn]);
                }
        }
    }

    // ---- epilogue: gelu(acc1)*acc3 -> g_act (fp16) ----
    __half* actb = g_act + (size_t)e * T * F;
    #pragma unroll
    for (int fm = 0; fm < 2; fm++) {
        int ml = wm * 32 + fm * 16 + g;
        #pragma unroll
        for (int fn = 0; fn < 4; fn++) {
            int col = n0 + wn * 32 + fn * 8 + 2 * t4;
            int ig0 = i0 + ml, ig1 = ig0 + 8;
            if (ig0 < cnt) {
                float g0 = acc1[fm][fn][0], g1 = acc1[fm][fn][1];
                __half2 v = __floats2half2_rn(g0 * normcdff(g0) * acc3[fm][fn][0],
                                              g1 * normcdff(g1) * acc3[fm][fn][1]);
                *reinterpret_cast<__half2*>(actb + (size_t)ig0 * F + col) = v;
            }
            if (ig1 < cnt) {
                float g2 = acc1[fm][fn][2], g3 = acc1[fm][fn][3];
                __half2 v = __floats2half2_rn(g2 * normcdff(g2) * acc3[fm][fn][2],
                                              g3 * normcdff(g3) * acc3[fm][fn][3]);
                *reinterpret_cast<__half2*>(actb + (size_t)ig1 * F + col) = v;
            }
        }
    }
}

// ================= gemm2: out[tok] += wgt * (act @ w2^T), fp16 mma =================
// CTA 128m x 128n, BK=64, 8 warps (warp 32x64), 3-stage cp.async.
// stage: A 128*144 + B 128*144 = 36864B; x3 = 110592B.
#define G2_STAGE_B 36864u
#define G2_OFF_B   18432u
#define G2_SMEM    (STAGES * G2_STAGE_B)

__global__ __launch_bounds__(256) void gemm2_mma(float* __restrict__ out) {
    extern __shared__ __half smem[];
    __shared__ int   s_tok[128];
    __shared__ float s_wt[128];

    int e = blockIdx.z;
    int cnt = g_cnt[e];
    int i0 = blockIdx.y * 128;
    if (i0 >= cnt) return;
    int n0 = blockIdx.x * 128;
    int tid = threadIdx.x;
    int wid = tid >> 5, lane = tid & 31;
    int g = lane >> 2, t4 = lane & 3;
    int wm = wid & 3, wn = wid >> 2;       // warp tile: m 32*wm, n 64*wn
    int mrows = min(128, cnt - i0);

    if (tid < 128) {
        int i = i0 + tid;
        s_tok[tid] = (i < cnt) ? g_tok[e][i] : -1;
        s_wt[tid]  = (i < cnt) ? g_wt[e][i]  : 0.0f;
    }
    __syncthreads();

    uint32_t sb = smem_u32(smem);
    const __half* Ag = g_act + ((size_t)e * T + i0) * F;
    const __half* Bg = c_w2 + ((size_t)e * H + n0) * F;

    auto stage = [&](int kc, int buf) {
        int k0 = kc * BK;
        uint32_t bb = sb + (uint32_t)buf * G2_STAGE_B;
        #pragma unroll
        for (int i = 0; i < 4; i++) {              // A (ragged)
            int id = tid + i * 256;
            int row = id >> 3, c4 = id & 7;
            bool v = row < mrows;
            const __half* src = v ? Ag + (size_t)row * F + k0 + c4 * 8 : Ag;
            cpa16(bb + (uint32_t)(row * 144 + c4 * 16), src, v ? 16u : 0u);
        }
        #pragma unroll
        for (int i = 0; i < 4; i++) {              // B
            int id = tid + i * 256;
            int row = id >> 3, c4 = id & 7;
            cpa16(bb + G2_OFF_B + (uint32_t)(row * 144 + c4 * 16),
                  Bg + (size_t)row * F + k0 + c4 * 8, 16u);
        }
    };

    float acc[2][8][4];
    #pragma unroll
    for (int a = 0; a < 2; a++)
        #pragma unroll
        for (int b = 0; b < 8; b++)
            #pragma unroll
            for (int c = 0; c < 4; c++) acc[a][b][c] = 0.f;

    stage(0, 0); CPA_COMMIT();
    stage(1, 1); CPA_COMMIT();

    const int NK = F / BK;   // 64
    for (int kc = 0; kc < NK; kc++) {
        int cur = kc % STAGES;
        CPA_WAIT(1);
        __syncthreads();
        if (kc + 2 < NK) stage(kc + 2, (kc + 2) % STAGES);
        CPA_COMMIT();

        const __half* As = smem + cur * (G2_STAGE_B / 2);
        const __half* Bs = As + G2_OFF_B / 2;

        #pragma unroll
        for (int ks = 0; ks < 4; ks++) {
            int kk = ks * 16 + 2 * t4;
            uint32_t a[2][4];
            #pragma unroll
            for (int fm = 0; fm < 2; fm++) {
                int r = wm * 32 + fm * 16 + g;
                a[fm][0] = lds32(As, r * PH + kk);
                a[fm][1] = lds32(As, (r + 8) * PH + kk);
                a[fm][2] = lds32(As, r * PH + kk + 8);
                a[fm][3] = lds32(As, (r + 8) * PH + kk + 8);
            }
            uint32_t b[8][2];
            #pragma unroll
            for (int fn = 0; fn < 8; fn++) {
                int r = wn * 64 + fn * 8 + g;
                b[fn][0] = lds32(Bs, r * PH + kk);
                b[fn][1] = lds32(Bs, r * PH + kk + 8);
            }
            #pragma unroll
            for (int fm = 0; fm < 2; fm++)
                #pragma unroll
                for (int fn = 0; fn < 8; fn++)
                    mma_f16(acc[fm][fn], a[fm], b[fn]);
        }
    }

    // ---- epilogue: 2 deterministic atomic adds per out element ----
    #pragma unroll
    for (int fm = 0; fm < 2; fm++) {
        int ml0 = wm * 32 + fm * 16 + g;
        int ml1 = ml0 + 8;
        int tok0 = s_tok[ml0], tok1 = s_tok[ml1];
        float w0 = s_wt[ml0], w1v = s_wt[ml1];
        #pragma unroll
        for (int fn = 0; fn < 8; fn++) {
            int col = n0 + wn * 64 + fn * 8 + 2 * t4;
            if (tok0 >= 0) {
                float* o = out + (size_t)tok0 * H + col;
                atomicAdd(o,     w0 * acc[fm][fn][0]);
                atomicAdd(o + 1, w0 * acc[fm][fn][1]);
            }
            if (tok1 >= 0) {
                float* o = out + (size_t)tok1 * H + col;
                atomicAdd(o,     w1v * acc[fm][fn][2]);
                atomicAdd(o + 1, w1v * acc[fm][fn][3]);
            }
        }
    }
}

// ---------------- launch ----------------
extern "C" void kernel_launch(void* const* d_in, const int* in_sizes, int n_in,
                              void* d_out, int out_size) {
    const float* hs = (const float*)d_in[0];
    const float* gw = (const float*)d_in[1];
    const float* w1 = (const float*)d_in[2];
    const float* w2 = (const float*)d_in[3];
    const float* w3 = (const float*)d_in[4];
    float* out = (float*)d_out;

    cudaFuncSetAttribute(gemm1_mma, cudaFuncAttributeMaxDynamicSharedMemorySize, G1_SMEM);
    cudaFuncSetAttribute(gemm2_mma, cudaFuncAttributeMaxDynamicSharedMemorySize, G2_SMEM);

    __half* d_hs; cudaGetSymbolAddress((void**)&d_hs, c_hs);
    __half* d_w1; cudaGetSymbolAddress((void**)&d_w1, c_w1);
    __half* d_w2; cudaGetSymbolAddress((void**)&d_w2, c_w2);
    __half* d_w3; cudaGetSymbolAddress((void**)&d_w3, c_w3);

    init_kernel<<<1024, 256>>>(out);
    router_kernel<<<T, 256>>>(hs, gw);
    cvt_kernel<<<4096, 256>>>((const float4*)hs, (uint2*)d_hs, T * H / 4);
    cvt_kernel<<<4096, 256>>>((const float4*)w1, (uint2*)d_w1, E * F * H / 4);
    cvt_kernel<<<4096, 256>>>((const float4*)w3, (uint2*)d_w3, E * F * H / 4);
    cvt_kernel<<<4096, 256>>>((const float4*)w2, (uint2*)d_w2, E * H * F / 4);
    gemm1_mma<<<dim3(F / 64, T / 128, E), 256, G1_SMEM>>>(hs);
    gemm2_mma<<<dim3(H / 128, T / 128, E), 256, G2_SMEM>>>(out);
}